// round 2
// baseline (speedup 1.0000x reference)
#include <cuda_runtime.h>
#include <cuda_bf16.h>
#include <math.h>

// ---------------- Problem constants ----------------
#define BATCH 2
#define SEQ 2048
#define BS 4096            // BATCH*SEQ
#define DIM 1024
#define NH 8
#define QC 128
#define QNOPE 96
#define QROPE 32
#define KVC 128
#define KNOPE 64
#define KROPE 64
#define VHD 256
#define DQK 128            // QNOPE+QROPE == KNOPE+KROPE
#define EPSV 1e-8f
#define SOFTMAX_SCALE 0.08838834764831845f  // 1/sqrt(128)

// ---------------- Scratch (device globals; no allocations allowed) ----------------
__device__ float g_cq[BS * QC];                 //  2 MB
__device__ float g_q[BS * (NH * DQK)];          // 16 MB
__device__ float g_ckvkr[BS * (KVC + KROPE)];   //  3 MB
__device__ float g_ckv[BS * KVC];               //  2 MB
__device__ float g_kv[BS * (NH * (KNOPE + VHD))]; // 40 MB
__device__ float g_Q[BATCH * NH * SEQ * DQK];   // 16 MB
__device__ float g_K[BATCH * NH * SEQ * DQK];   // 16 MB
__device__ float g_V[BATCH * NH * SEQ * VHD];   // 32 MB
__device__ float g_attn[BS * (NH * VHD)];       // 32 MB

// ---------------- Generic fp32 tiled GEMM:  C = A[M,K] @ W[K,N] + bias ----------------
#define GBM 128
#define GBN 64
#define GBK 16

__global__ __launch_bounds__(256) void gemm_bias_kernel(
    const float* __restrict__ A, const float* __restrict__ W,
    const float* __restrict__ bias, float* __restrict__ C,
    int M, int N, int K)
{
    __shared__ float As[GBM][GBK + 1];   // [m][k], padded
    __shared__ float Ws[GBK][GBN];       // [k][n]

    const int bm = blockIdx.y * GBM;
    const int bn = blockIdx.x * GBN;
    const int tid = threadIdx.x;
    const int tx = tid & 15;   // n-group: cols tx*4..tx*4+3
    const int ty = tid >> 4;   // m-group: rows ty*8..ty*8+7

    float acc[8][4];
#pragma unroll
    for (int i = 0; i < 8; i++)
#pragma unroll
        for (int j = 0; j < 4; j++) acc[i][j] = 0.f;

    for (int k0 = 0; k0 < K; k0 += GBK) {
        // Load A tile: 128x16 floats = 512 float4, 2 per thread
#pragma unroll
        for (int t = 0; t < 2; t++) {
            int idx = tid * 2 + t;            // 0..511
            int row = idx >> 2;
            int kq = (idx & 3) * 4;
            float4 v = *(const float4*)&A[(size_t)(bm + row) * K + k0 + kq];
            As[row][kq + 0] = v.x; As[row][kq + 1] = v.y;
            As[row][kq + 2] = v.z; As[row][kq + 3] = v.w;
        }
        // Load W tile: 16x64 = 256 float4, 1 per thread
        {
            int k = tid >> 4;
            int n4 = (tid & 15) * 4;
            *(float4*)&Ws[k][n4] = *(const float4*)&W[(size_t)(k0 + k) * N + bn + n4];
        }
        __syncthreads();

#pragma unroll
        for (int kk = 0; kk < GBK; kk++) {
            float a[8];
#pragma unroll
            for (int i = 0; i < 8; i++) a[i] = As[ty * 8 + i][kk];
            float4 w = *(const float4*)&Ws[kk][tx * 4];
#pragma unroll
            for (int i = 0; i < 8; i++) {
                acc[i][0] += a[i] * w.x;
                acc[i][1] += a[i] * w.y;
                acc[i][2] += a[i] * w.z;
                acc[i][3] += a[i] * w.w;
            }
        }
        __syncthreads();
    }

    const int col = bn + tx * 4;
    float4 b4 = *(const float4*)&bias[col];
#pragma unroll
    for (int i = 0; i < 8; i++) {
        int row = bm + ty * 8 + i;
        float4 o;
        o.x = acc[i][0] + b4.x;
        o.y = acc[i][1] + b4.y;
        o.z = acc[i][2] + b4.z;
        o.w = acc[i][3] + b4.w;
        *(float4*)&C[(size_t)row * N + col] = o;
    }
}

// ---------------- RMSNorm over 128 cols (strided input) ----------------
__global__ void rmsnorm_kernel(const float* __restrict__ in, int in_stride,
                               const float* __restrict__ w,
                               float* __restrict__ out, int out_stride)
{
    __shared__ float red[128];
    const int row = blockIdx.x;
    const int c = threadIdx.x;
    float v = in[(size_t)row * in_stride + c];
    red[c] = v * v;
    __syncthreads();
#pragma unroll
    for (int o = 64; o > 0; o >>= 1) {
        if (c < o) red[c] += red[c + o];
        __syncthreads();
    }
    float ms = red[0] * (1.f / 128.f) + EPSV;
    out[(size_t)row * out_stride + c] = w[c] * v * rsqrtf(ms);
}

// ---------------- Assemble Q (nope copy + rope) ----------------
__global__ void assemble_q_kernel(const int* __restrict__ pos)
{
    const int s = blockIdx.x;
    const int bh = blockIdx.y;
    const int b = bh >> 3, h = bh & 7;
    const int c = threadIdx.x;    // 0..127
    const float* qrow = g_q + (size_t)(b * SEQ + s) * (NH * DQK);
    float v;
    if (c < QNOPE) {
        v = qrow[h * QNOPE + c];
    } else {
        int rc = c - QNOPE;              // 0..31
        int i = rc >> 1;                 // freq index
        const float* rr = qrow + NH * QNOPE + h * QROPE;
        float xe = rr[2 * i];
        float xo = rr[2 * i + 1];
        float p = (float)pos[b * SEQ + s];
        float fr = powf(10000.0f, -(2.0f * (float)i) / (float)QROPE);
        float ang = p * fr;
        float cs = cosf(ang), sn = sinf(ang);
        v = (rc & 1) ? (xe * sn + xo * cs) : (xe * cs - xo * sn);
    }
    g_Q[((size_t)bh * SEQ + s) * DQK + c] = v;
}

// ---------------- Assemble K (per-head nope + broadcast rope) ----------------
__global__ void assemble_k_kernel(const int* __restrict__ pos)
{
    const int s = blockIdx.x;
    const int b = blockIdx.y;
    const int c = threadIdx.x;    // 0..127
    if (c < KNOPE) {
        const float* kvrow = g_kv + (size_t)(b * SEQ + s) * (NH * (KNOPE + VHD));
#pragma unroll
        for (int h = 0; h < NH; h++)
            g_K[((size_t)(b * NH + h) * SEQ + s) * DQK + c] = kvrow[h * KNOPE + c];
    } else {
        int rc = c - KNOPE;              // 0..63
        int i = rc >> 1;
        const float* kr = g_ckvkr + (size_t)(b * SEQ + s) * (KVC + KROPE) + KVC;
        float xe = kr[2 * i];
        float xo = kr[2 * i + 1];
        float p = (float)pos[b * SEQ + s];
        float fr = powf(10000.0f, -(2.0f * (float)i) / (float)KROPE);
        float ang = p * fr;
        float cs = cosf(ang), sn = sinf(ang);
        float v = (rc & 1) ? (xe * sn + xo * cs) : (xe * cs - xo * sn);
#pragma unroll
        for (int h = 0; h < NH; h++)
            g_K[((size_t)(b * NH + h) * SEQ + s) * DQK + c] = v;
    }
}

// ---------------- Assemble V (layout copy) ----------------
__global__ void assemble_v_kernel()
{
    // total float4: BATCH*NH*SEQ*VHD/4 = 2,097,152
    int idx = blockIdx.x * blockDim.x + threadIdx.x;
    int c4 = idx & 63;                  // 64 float4 per (bh,s) row
    int row = idx >> 6;                 // 0..32767
    int s = row & (SEQ - 1);
    int bh = row >> 11;
    int b = bh >> 3, h = bh & 7;
    const float4* src = (const float4*)g_kv;
    float4 v = src[(size_t)(b * SEQ + s) * 640 + 128 + h * 64 + c4];
    ((float4*)g_V)[(size_t)idx] = v;
}

// ---------------- Flash attention (fp32, online softmax) ----------------
// grid: (32 q-tiles, 16 bh), 256 threads.
// thread (rg = tid/16, cg = tid%16): owns rows rg*4..+3
//   S cols: {cg, cg+16};  O cols: j*64 + cg*4 + t (j<4, t<4)
#define QT 64
#define KT 32
#define QS_STRIDE 132
#define KS_STRIDE 132
#define PS_STRIDE 33
#define ATT_SMEM_FLOATS (QT*QS_STRIDE + KT*KS_STRIDE + KT*VHD + QT*PS_STRIDE)

__global__ __launch_bounds__(256, 2) void attn_kernel()
{
    extern __shared__ float sm[];
    float* Qs = sm;                                  // [64][132]
    float* Ks = Qs + QT * QS_STRIDE;                 // [32][132]
    float* Vs = Ks + KT * KS_STRIDE;                 // [32][256]
    float* Ps = Vs + KT * VHD;                       // [64][33]

    const int qt = blockIdx.x;
    const int bh = blockIdx.y;
    const int tid = threadIdx.x;
    const int rg = tid >> 4;      // 0..15
    const int cg = tid & 15;      // 0..15

    const float* Qg = g_Q + ((size_t)bh * SEQ + qt * QT) * DQK;
    const float* Kg = g_K + (size_t)bh * SEQ * DQK;
    const float* Vg = g_V + (size_t)bh * SEQ * VHD;

    // Load Q tile (64x128 = 2048 float4, 8 per thread)
#pragma unroll
    for (int t = 0; t < 8; t++) {
        int idx = tid + t * 256;
        int r = idx >> 5;
        int c4 = idx & 31;
        float4 v = ((const float4*)Qg)[idx];
        *(float4*)&Qs[r * QS_STRIDE + c4 * 4] = v;
    }

    float acc[4][16];
#pragma unroll
    for (int i = 0; i < 4; i++)
#pragma unroll
        for (int j = 0; j < 16; j++) acc[i][j] = 0.f;
    float mrow[4], lrow[4];
#pragma unroll
    for (int i = 0; i < 4; i++) { mrow[i] = -1e30f; lrow[i] = 0.f; }

    for (int kt = 0; kt < SEQ / KT; kt++) {
        // Load K tile (32x128 = 1024 f4, 4/thread) and V tile (32x256 = 2048 f4, 8/thread)
        const float4* K4 = (const float4*)(Kg + (size_t)kt * KT * DQK);
#pragma unroll
        for (int t = 0; t < 4; t++) {
            int idx = tid + t * 256;
            int r = idx >> 5;
            int c4 = idx & 31;
            float4 v = K4[idx];
            *(float4*)&Ks[r * KS_STRIDE + c4 * 4] = v;
        }
        const float4* V4 = (const float4*)(Vg + (size_t)kt * KT * VHD);
#pragma unroll
        for (int t = 0; t < 8; t++) {
            int idx = tid + t * 256;
            ((float4*)Vs)[idx] = V4[idx];
        }
        __syncthreads();

        // ---- S = Q K^T for this thread's 4 rows x 2 cols (cg, cg+16) ----
        float s0[4] = {0.f, 0.f, 0.f, 0.f};
        float s1[4] = {0.f, 0.f, 0.f, 0.f};
        const float* k0p = &Ks[cg * KS_STRIDE];
        const float* k1p = &Ks[(cg + 16) * KS_STRIDE];
#pragma unroll
        for (int c4 = 0; c4 < 32; c4++) {
            float4 k0 = *(const float4*)&k0p[c4 * 4];
            float4 k1 = *(const float4*)&k1p[c4 * 4];
#pragma unroll
            for (int i = 0; i < 4; i++) {
                float4 q = *(const float4*)&Qs[(rg * 4 + i) * QS_STRIDE + c4 * 4];
                s0[i] += q.x * k0.x + q.y * k0.y + q.z * k0.z + q.w * k0.w;
                s1[i] += q.x * k1.x + q.y * k1.y + q.z * k1.z + q.w * k1.w;
            }
        }

        // ---- Online softmax (row reductions across the 16 cg lanes) ----
#pragma unroll
        for (int i = 0; i < 4; i++) {
            float a = s0[i] * SOFTMAX_SCALE;
            float b = s1[i] * SOFTMAX_SCALE;
            float mx = fmaxf(a, b);
#pragma unroll
            for (int o = 8; o >= 1; o >>= 1)
                mx = fmaxf(mx, __shfl_xor_sync(0xffffffffu, mx, o));
            float mnew = fmaxf(mrow[i], mx);
            float al = __expf(mrow[i] - mnew);
            float p0 = __expf(a - mnew);
            float p1 = __expf(b - mnew);
            float ss = p0 + p1;
#pragma unroll
            for (int o = 8; o >= 1; o >>= 1)
                ss += __shfl_xor_sync(0xffffffffu, ss, o);
            lrow[i] = lrow[i] * al + ss;
            mrow[i] = mnew;
            Ps[(rg * 4 + i) * PS_STRIDE + cg] = p0;
            Ps[(rg * 4 + i) * PS_STRIDE + cg + 16] = p1;
#pragma unroll
            for (int j = 0; j < 16; j++) acc[i][j] *= al;
        }
        __syncthreads();

        // ---- O += P @ V ----
#pragma unroll 4
        for (int k = 0; k < KT; k++) {
            float pr0 = Ps[(rg * 4 + 0) * PS_STRIDE + k];
            float pr1 = Ps[(rg * 4 + 1) * PS_STRIDE + k];
            float pr2 = Ps[(rg * 4 + 2) * PS_STRIDE + k];
            float pr3 = Ps[(rg * 4 + 3) * PS_STRIDE + k];
            const float* vrow = &Vs[k * VHD + cg * 4];
#pragma unroll
            for (int j = 0; j < 4; j++) {
                float4 v = *(const float4*)&vrow[j * 64];
                acc[0][j * 4 + 0] += pr0 * v.x; acc[0][j * 4 + 1] += pr0 * v.y;
                acc[0][j * 4 + 2] += pr0 * v.z; acc[0][j * 4 + 3] += pr0 * v.w;
                acc[1][j * 4 + 0] += pr1 * v.x; acc[1][j * 4 + 1] += pr1 * v.y;
                acc[1][j * 4 + 2] += pr1 * v.z; acc[1][j * 4 + 3] += pr1 * v.w;
                acc[2][j * 4 + 0] += pr2 * v.x; acc[2][j * 4 + 1] += pr2 * v.y;
                acc[2][j * 4 + 2] += pr2 * v.z; acc[2][j * 4 + 3] += pr2 * v.w;
                acc[3][j * 4 + 0] += pr3 * v.x; acc[3][j * 4 + 1] += pr3 * v.y;
                acc[3][j * 4 + 2] += pr3 * v.z; acc[3][j * 4 + 3] += pr3 * v.w;
            }
        }
        __syncthreads();
    }

    // ---- Epilogue: divide by l, write to g_attn[(b,s), h*256 + col] ----
    const int b = bh >> 3, h = bh & 7;
#pragma unroll
    for (int i = 0; i < 4; i++) {
        float inv = 1.f / lrow[i];
        int srow = qt * QT + rg * 4 + i;
        float* orow = g_attn + ((size_t)(b * SEQ + srow)) * (NH * VHD) + h * VHD;
#pragma unroll
        for (int j = 0; j < 4; j++) {
            float4 o;
            o.x = acc[i][j * 4 + 0] * inv;
            o.y = acc[i][j * 4 + 1] * inv;
            o.z = acc[i][j * 4 + 2] * inv;
            o.w = acc[i][j * 4 + 3] * inv;
            *(float4*)&orow[j * 64 + cg * 4] = o;
        }
    }
}

// ---------------- Launch ----------------
extern "C" void kernel_launch(void* const* d_in, const int* in_sizes, int n_in,
                              void* d_out, int out_size)
{
    const float* x        = (const float*)d_in[0];
    const int*   pos      = (const int*)d_in[1];
    const float* w_dq_w   = (const float*)d_in[2];
    const float* w_dq_b   = (const float*)d_in[3];
    const float* q_norm_w = (const float*)d_in[4];
    const float* w_uq_w   = (const float*)d_in[5];
    const float* w_uq_b   = (const float*)d_in[6];
    const float* w_dkv_w  = (const float*)d_in[7];
    const float* w_dkv_b  = (const float*)d_in[8];
    const float* kv_norm_w= (const float*)d_in[9];
    const float* w_ukv_w  = (const float*)d_in[10];
    const float* w_ukv_b  = (const float*)d_in[11];
    const float* w_o_w    = (const float*)d_in[12];
    const float* w_o_b    = (const float*)d_in[13];
    float* out = (float*)d_out;

    float *cq, *q, *ckvkr, *ckv, *kv, *attn;
    cudaGetSymbolAddress((void**)&cq, g_cq);
    cudaGetSymbolAddress((void**)&q, g_q);
    cudaGetSymbolAddress((void**)&ckvkr, g_ckvkr);
    cudaGetSymbolAddress((void**)&ckv, g_ckv);
    cudaGetSymbolAddress((void**)&kv, g_kv);
    cudaGetSymbolAddress((void**)&attn, g_attn);

    // 1) cq_raw = x @ w_dq + b      [4096,1024]@[1024,128]
    gemm_bias_kernel<<<dim3(QC / GBN, BS / GBM), 256>>>(x, w_dq_w, w_dq_b, cq, BS, QC, DIM);
    // 2) cq = rmsnorm(cq_raw) * q_norm_w  (in-place)
    rmsnorm_kernel<<<BS, 128>>>(cq, QC, q_norm_w, cq, QC);
    // 3) q = cq @ w_uq_qr + b       [4096,128]@[128,1024]
    gemm_bias_kernel<<<dim3((NH * DQK) / GBN, BS / GBM), 256>>>(cq, w_uq_w, w_uq_b, q, BS, NH * DQK, QC);
    // 4) ckv_kr = x @ w_dkv_kr + b  [4096,1024]@[1024,192]
    gemm_bias_kernel<<<dim3((KVC + KROPE) / GBN, BS / GBM), 256>>>(x, w_dkv_w, w_dkv_b, ckvkr, BS, KVC + KROPE, DIM);
    // 5) ckv = rmsnorm(ckv_kr[:, :128]) * kv_norm_w
    rmsnorm_kernel<<<BS, 128>>>(ckvkr, KVC + KROPE, kv_norm_w, ckv, KVC);
    // 6) kv = ckv @ w_uk_uv + b     [4096,128]@[128,2560]
    gemm_bias_kernel<<<dim3((NH * (KNOPE + VHD)) / GBN, BS / GBM), 256>>>(ckv, w_ukv_w, w_ukv_b, kv, BS, NH * (KNOPE + VHD), KVC);
    // 7-9) assemble Q (rope), K (rope + broadcast), V
    assemble_q_kernel<<<dim3(SEQ, BATCH * NH), 128>>>(pos);
    assemble_k_kernel<<<dim3(SEQ, BATCH), 128>>>(pos);
    assemble_v_kernel<<<(BATCH * NH * SEQ * VHD / 4) / 256, 256>>>();
    // 10) flash attention
    cudaFuncSetAttribute(attn_kernel, cudaFuncAttributeMaxDynamicSharedMemorySize,
                         ATT_SMEM_FLOATS * (int)sizeof(float));
    attn_kernel<<<dim3(SEQ / QT, BATCH * NH), 256, ATT_SMEM_FLOATS * sizeof(float)>>>();
    // 11) out = attn @ w_o + b      [4096,2048]@[2048,1024]
    gemm_bias_kernel<<<dim3(DIM / GBN, BS / GBM), 256>>>(attn, w_o_w, w_o_b, out, BS, DIM, NH * VHD);
}

// round 6
// speedup vs baseline: 2.4192x; 2.4192x over previous
#include <cuda_runtime.h>
#include <cuda_bf16.h>
#include <cstdint>
#include <math.h>

typedef __nv_bfloat16 bf16;

// ---------------- Problem constants ----------------
#define BATCH 2
#define SEQ 2048
#define BS 4096
#define DIM 1024
#define NH 8
#define QC 128
#define QNOPE 96
#define QROPE 32
#define KVC 128
#define KNOPE 64
#define KROPE 64
#define VHD 256
#define DQK 128
#define EPSV 1e-8f
#define SOFTMAX_SCALE 0.08838834764831845f

// ---------------- Scratch (device globals) ----------------
__device__ float g_cq[BS * QC];
__device__ float g_q[BS * NH * DQK];
__device__ float g_ckvkr[BS * (KVC + KROPE)];
__device__ float g_kv[BS * NH * (KNOPE + VHD)];
__device__ float g_attn[BS * NH * VHD];
__device__ float g_S[16 * SEQ * SEQ];                   // 256 MB scores

__device__ bf16 g_xh[BS * DIM],  g_xl[BS * DIM];
__device__ bf16 g_cqh[BS * QC],  g_cql[BS * QC];
__device__ bf16 g_ckvh[BS * KVC], g_ckvl[BS * KVC];
__device__ bf16 g_Qh[BATCH * NH * SEQ * DQK], g_Ql[BATCH * NH * SEQ * DQK];
__device__ bf16 g_Kh[BATCH * NH * SEQ * DQK], g_Kl[BATCH * NH * SEQ * DQK];
__device__ bf16 g_Vth[BATCH * NH * VHD * SEQ], g_Vtl[BATCH * NH * VHD * SEQ];
__device__ bf16 g_Ph[16 * SEQ * SEQ], g_Pl[16 * SEQ * SEQ];
__device__ bf16 g_attnh[BS * NH * VHD], g_attnl[BS * NH * VHD];
__device__ bf16 g_wdqh[QC * DIM],  g_wdql[QC * DIM];
__device__ bf16 g_wuqh[NH * DQK * QC], g_wuql[NH * DQK * QC];
__device__ bf16 g_wdkvh[(KVC + KROPE) * DIM], g_wdkvl[(KVC + KROPE) * DIM];
__device__ bf16 g_wukvh[NH * (KNOPE + VHD) * KVC], g_wukvl[NH * (KNOPE + VHD) * KVC];
__device__ bf16 g_woh[DIM * NH * VHD], g_wol[DIM * NH * VHD];

__device__ __forceinline__ void bsplit(float x, bf16& h, bf16& l) {
    h = __float2bfloat16(x);
    l = __float2bfloat16(x - __bfloat162float(h));
}
__device__ __forceinline__ uint32_t smem_u32(const void* p) {
    uint32_t a;
    asm("{ .reg .u64 t; cvta.to.shared.u64 t, %1; cvt.u32.u64 %0, t; }" : "=r"(a) : "l"(p));
    return a;
}
__device__ __forceinline__ void cp16(uint32_t s, const void* g) {
    asm volatile("cp.async.ca.shared.global [%0], [%1], 16;" :: "r"(s), "l"(g));
}
#define CP_COMMIT() asm volatile("cp.async.commit_group;" ::: "memory")
#define CP_WAIT0()  asm volatile("cp.async.wait_group 0;" ::: "memory")
#define CP_WAIT1()  asm volatile("cp.async.wait_group 1;" ::: "memory")

__device__ __forceinline__ void lds4(uint32_t addr, uint32_t* r) {
    asm volatile("ldmatrix.sync.aligned.m8n8.x4.shared.b16 {%0,%1,%2,%3}, [%4];"
                 : "=r"(r[0]), "=r"(r[1]), "=r"(r[2]), "=r"(r[3]) : "r"(addr));
}
__device__ __forceinline__ void mma16816(float* c, const uint32_t* a, uint32_t b0, uint32_t b1) {
    asm volatile("mma.sync.aligned.m16n8k16.row.col.f32.bf16.bf16.f32 "
                 "{%0,%1,%2,%3}, {%4,%5,%6,%7}, {%8,%9}, {%0,%1,%2,%3};"
                 : "+f"(c[0]), "+f"(c[1]), "+f"(c[2]), "+f"(c[3])
                 : "r"(a[0]), "r"(a[1]), "r"(a[2]), "r"(a[3]), "r"(b0), "r"(b1));
}

// ---------------- Elementwise fp32 -> bf16 hi/lo split ----------------
__global__ __launch_bounds__(256) void convert_split_kernel(
    const float* __restrict__ in, bf16* __restrict__ h, bf16* __restrict__ l, int n4)
{
    int i = blockIdx.x * 256 + threadIdx.x;
    if (i >= n4) return;
    float4 v = ((const float4*)in)[i];
    bf16 h0, h1, h2, h3, l0, l1, l2, l3;
    bsplit(v.x, h0, l0); bsplit(v.y, h1, l1); bsplit(v.z, h2, l2); bsplit(v.w, h3, l3);
    ((__nv_bfloat162*)h)[i * 2 + 0] = __halves2bfloat162(h0, h1);
    ((__nv_bfloat162*)h)[i * 2 + 1] = __halves2bfloat162(h2, h3);
    ((__nv_bfloat162*)l)[i * 2 + 0] = __halves2bfloat162(l0, l1);
    ((__nv_bfloat162*)l)[i * 2 + 1] = __halves2bfloat162(l2, l3);
}

// ---------------- Transposed fp32 [R,C] -> bf16 hi/lo [C,R] ----------------
__global__ void transpose_split_kernel(const float* __restrict__ src, int R, int C,
                                       bf16* __restrict__ h, bf16* __restrict__ l)
{
    __shared__ float t[32][33];
    int c0 = blockIdx.x * 32, r0 = blockIdx.y * 32;
    int tx = threadIdx.x, ty = threadIdx.y;
#pragma unroll
    for (int i = 0; i < 4; i++)
        t[ty + i * 8][tx] = src[(size_t)(r0 + ty + i * 8) * C + c0 + tx];
    __syncthreads();
#pragma unroll
    for (int i = 0; i < 4; i++) {
        int orow = c0 + ty + i * 8, oc = r0 + tx;
        bf16 hh, ll; bsplit(t[tx][ty + i * 8], hh, ll);
        h[(size_t)orow * R + oc] = hh;
        l[(size_t)orow * R + oc] = ll;
    }
}

// ---------------- V slice of g_kv -> transposed bf16 hi/lo [bh][256][2048] ----------------
__global__ void vt_split_kernel()
{
    __shared__ float t[32][33];
    int s0 = blockIdx.x * 32, d0 = blockIdx.y * 32, z = blockIdx.z;
    int b = z >> 3, hh_ = z & 7;
    int tx = threadIdx.x, ty = threadIdx.y;
#pragma unroll
    for (int i = 0; i < 4; i++)
        t[ty + i * 8][tx] =
            g_kv[(size_t)(b * SEQ + s0 + ty + i * 8) * (NH * (KNOPE + VHD)) + NH * KNOPE + hh_ * VHD + d0 + tx];
    __syncthreads();
#pragma unroll
    for (int i = 0; i < 4; i++) {
        size_t o = (size_t)(z * VHD + d0 + ty + i * 8) * SEQ + s0 + tx;
        bf16 hv, lv; bsplit(t[tx][ty + i * 8], hv, lv);
        g_Vth[o] = hv; g_Vtl[o] = lv;
    }
}

// ---------------- RMSNorm (128 cols) -> bf16 hi/lo ----------------
__global__ void rmsnorm_split_kernel(const float* __restrict__ in, int stride,
                                     const float* __restrict__ w,
                                     bf16* __restrict__ h, bf16* __restrict__ l)
{
    __shared__ float red[128];
    const int row = blockIdx.x, c = threadIdx.x;
    float v = in[(size_t)row * stride + c];
    red[c] = v * v;
    __syncthreads();
#pragma unroll
    for (int o = 64; o > 0; o >>= 1) { if (c < o) red[c] += red[c + o]; __syncthreads(); }
    float r = w[c] * v * rsqrtf(red[0] * (1.f / 128.f) + EPSV);
    bf16 hh, ll; bsplit(r, hh, ll);
    h[(size_t)row * 128 + c] = hh;
    l[(size_t)row * 128 + c] = ll;
}

// ---------------- Assemble Q (nope + rope) -> bf16 hi/lo [bh][s][128] ----------------
__global__ void assemble_q_kernel(const int* __restrict__ pos)
{
    const int s = blockIdx.x, bh = blockIdx.y;
    const int b = bh >> 3, h = bh & 7, c = threadIdx.x;
    const float* qrow = g_q + (size_t)(b * SEQ + s) * (NH * DQK);
    float v;
    if (c < QNOPE) v = qrow[h * QNOPE + c];
    else {
        int rc = c - QNOPE, i = rc >> 1;
        const float* rr = qrow + NH * QNOPE + h * QROPE;
        float xe = rr[2 * i], xo = rr[2 * i + 1];
        float p = (float)pos[b * SEQ + s];
        float ang = p * powf(10000.0f, -(2.0f * (float)i) / (float)QROPE);
        float cs = cosf(ang), sn = sinf(ang);
        v = (rc & 1) ? (xe * sn + xo * cs) : (xe * cs - xo * sn);
    }
    size_t o = ((size_t)bh * SEQ + s) * DQK + c;
    bf16 hh, ll; bsplit(v, hh, ll);
    g_Qh[o] = hh; g_Ql[o] = ll;
}

// ---------------- Assemble K -> bf16 hi/lo [bh][s][128] ----------------
__global__ void assemble_k_kernel(const int* __restrict__ pos)
{
    const int s = blockIdx.x, b = blockIdx.y, c = threadIdx.x;
    if (c < KNOPE) {
        const float* kvrow = g_kv + (size_t)(b * SEQ + s) * (NH * (KNOPE + VHD));
#pragma unroll
        for (int h = 0; h < NH; h++) {
            float x = kvrow[h * KNOPE + c];
            size_t o = ((size_t)(b * NH + h) * SEQ + s) * DQK + c;
            bf16 hh, ll; bsplit(x, hh, ll);
            g_Kh[o] = hh; g_Kl[o] = ll;
        }
        return;
    }
    int rc = c - KNOPE, i = rc >> 1;
    const float* kr = g_ckvkr + (size_t)(b * SEQ + s) * (KVC + KROPE) + KVC;
    float xe = kr[2 * i], xo = kr[2 * i + 1];
    float p = (float)pos[b * SEQ + s];
    float ang = p * powf(10000.0f, -(2.0f * (float)i) / (float)KROPE);
    float cs = cosf(ang), sn = sinf(ang);
    float v = (rc & 1) ? (xe * sn + xo * cs) : (xe * cs - xo * sn);
    bf16 hh, ll; bsplit(v, hh, ll);
#pragma unroll
    for (int h = 0; h < NH; h++) {
        size_t o = ((size_t)(b * NH + h) * SEQ + s) * DQK + c;
        g_Kh[o] = hh; g_Kl[o] = ll;
    }
}

// ---------------- Softmax over 2048 cols -> bf16 hi/lo P ----------------
__global__ __launch_bounds__(256) void softmax_split_kernel()
{
    __shared__ float sred[8], sred2[8];
    size_t r = blockIdx.x;
    const float4* row = (const float4*)(g_S + r * SEQ);
    int t = threadIdx.x, lane = t & 31, w = t >> 5;
    float4 v0 = row[t], v1 = row[t + 256];
    float mx = fmaxf(fmaxf(fmaxf(v0.x, v0.y), fmaxf(v0.z, v0.w)),
                     fmaxf(fmaxf(v1.x, v1.y), fmaxf(v1.z, v1.w)));
#pragma unroll
    for (int o = 16; o >= 1; o >>= 1) mx = fmaxf(mx, __shfl_xor_sync(0xffffffffu, mx, o));
    if (lane == 0) sred[w] = mx;
    __syncthreads();
    float mall = sred[0];
#pragma unroll
    for (int i = 1; i < 8; i++) mall = fmaxf(mall, sred[i]);
    float e[8];
    e[0] = __expf(v0.x - mall); e[1] = __expf(v0.y - mall);
    e[2] = __expf(v0.z - mall); e[3] = __expf(v0.w - mall);
    e[4] = __expf(v1.x - mall); e[5] = __expf(v1.y - mall);
    e[6] = __expf(v1.z - mall); e[7] = __expf(v1.w - mall);
    float s = e[0] + e[1] + e[2] + e[3] + e[4] + e[5] + e[6] + e[7];
#pragma unroll
    for (int o = 16; o >= 1; o >>= 1) s += __shfl_xor_sync(0xffffffffu, s, o);
    if (lane == 0) sred2[w] = s;
    __syncthreads();
    float tot = sred2[0];
#pragma unroll
    for (int i = 1; i < 8; i++) tot += sred2[i];
    float inv = 1.f / tot;
    bf16 h[8], l[8];
#pragma unroll
    for (int i = 0; i < 8; i++) bsplit(e[i] * inv, h[i], l[i]);
    __nv_bfloat162* Ph2 = (__nv_bfloat162*)(g_Ph + r * SEQ);
    __nv_bfloat162* Pl2 = (__nv_bfloat162*)(g_Pl + r * SEQ);
    Ph2[t * 2 + 0] = __halves2bfloat162(h[0], h[1]);
    Ph2[t * 2 + 1] = __halves2bfloat162(h[2], h[3]);
    Ph2[512 + t * 2 + 0] = __halves2bfloat162(h[4], h[5]);
    Ph2[512 + t * 2 + 1] = __halves2bfloat162(h[6], h[7]);
    Pl2[t * 2 + 0] = __halves2bfloat162(l[0], l[1]);
    Pl2[t * 2 + 1] = __halves2bfloat162(l[2], l[3]);
    Pl2[512 + t * 2 + 0] = __halves2bfloat162(l[4], l[5]);
    Pl2[512 + t * 2 + 1] = __halves2bfloat162(l[6], l[7]);
}

// ---------------- mma.sync bf16x3 GEMM ----------------
// C[M,N] = scale * (A @ B^T) + bias.  A=[M,K] hi/lo, B=[N,K] hi/lo (K-major).
// Block 128x64, BK=32, 8 warps (warp tile 32x32), cp.async double buffer.
// Stage layout (bytes): Ah 0..10240 (128 rows * 80B), Al +10240,
//                       Bh +20480 (64 rows * 80B = 5120), Bl +25600. Stage = 30720.
#define AST 80
#define STAGE_B 30720
#define GEMM_SMEM (2 * STAGE_B)

__global__ __launch_bounds__(256, 2) void mma_gemm_kernel(
    const bf16* __restrict__ Ah, const bf16* __restrict__ Al,
    const bf16* __restrict__ Bh, const bf16* __restrict__ Bl,
    const float* __restrict__ bias, float* __restrict__ C,
    int K, int ldc,
    long long sA, long long sB, long long sCb, long long sCh, float scale)
{
    extern __shared__ char smem[];
    uint32_t sb = smem_u32(smem);
    const int tid = threadIdx.x;
    const int wid = tid >> 5, lane = tid & 31;
    const int wr = wid >> 1, wc = wid & 1;      // warp grid 4x2, warp tile 32x32
    const int bm = blockIdx.y * 128, bn = blockIdx.x * 64;
    const int z = blockIdx.z;
    Ah += (size_t)z * sA; Al += (size_t)z * sA;
    Bh += (size_t)z * sB; Bl += (size_t)z * sB;
    float* Cp = C + (size_t)(z >> 3) * sCb + (size_t)(z & 7) * sCh;

    const int NC = K >> 5;

    auto load_stage = [&](int c, int s) {
        uint32_t base = sb + s * STAGE_B;
        int k0 = c << 5;
#pragma unroll
        for (int t = 0; t < 2; t++) {
            int idx = tid + t * 256;
            int row = idx >> 2, ch = idx & 3;
            size_t go = (size_t)(bm + row) * K + k0 + ch * 8;
            uint32_t so = base + row * AST + ch * 16;
            cp16(so, Ah + go);
            cp16(so + 10240, Al + go);
        }
        {
            int row = tid >> 2, ch = tid & 3;
            size_t go = (size_t)(bn + row) * K + k0 + ch * 8;
            uint32_t so = base + 20480 + row * AST + ch * 16;
            cp16(so, Bh + go);
            cp16(so + 5120, Bl + go);
        }
        CP_COMMIT();
    };

    float acc[2][4][4];
#pragma unroll
    for (int i = 0; i < 2; i++)
#pragma unroll
        for (int j = 0; j < 4; j++)
#pragma unroll
            for (int q = 0; q < 4; q++) acc[i][j][q] = 0.f;

    load_stage(0, 0);

    for (int c = 0; c < NC; c++) {
        if (c + 1 < NC) { load_stage(c + 1, (c + 1) & 1); CP_WAIT1(); }
        else CP_WAIT0();
        __syncthreads();

        uint32_t base = sb + (c & 1) * STAGE_B;
#pragma unroll
        for (int kk = 0; kk < 2; kk++) {
            int ch = kk * 2 + (lane >> 4);
            uint32_t ah[2][4], al[2][4], bh[2][4], bl[2][4];
#pragma unroll
            for (int mi = 0; mi < 2; mi++) {
                int r = wr * 32 + mi * 16 + (lane & 15);
                uint32_t ad = base + r * AST + ch * 16;
                lds4(ad, ah[mi]);
                lds4(ad + 10240, al[mi]);
            }
#pragma unroll
            for (int ni = 0; ni < 2; ni++) {
                int r = wc * 32 + ni * 16 + (lane & 15);
                uint32_t bd = base + 20480 + r * AST + ch * 16;
                lds4(bd, bh[ni]);
                lds4(bd + 5120, bl[ni]);
            }
#pragma unroll
            for (int mi = 0; mi < 2; mi++)
#pragma unroll
                for (int ni = 0; ni < 2; ni++)
#pragma unroll
                    for (int sub = 0; sub < 2; sub++) {
                        int nj = ni * 2 + sub;
                        mma16816(acc[mi][nj], ah[mi], bh[ni][sub], bh[ni][sub + 2]);
                        mma16816(acc[mi][nj], ah[mi], bl[ni][sub], bl[ni][sub + 2]);
                        mma16816(acc[mi][nj], al[mi], bh[ni][sub], bh[ni][sub + 2]);
                    }
        }
        __syncthreads();
    }

    // Epilogue
    const int g = lane >> 2, q = lane & 3;
#pragma unroll
    for (int mi = 0; mi < 2; mi++) {
#pragma unroll
        for (int nj = 0; nj < 4; nj++) {
            int col = bn + wc * 32 + nj * 8 + q * 2;
            float bx = 0.f, by = 0.f;
            if (bias) { bx = bias[col]; by = bias[col + 1]; }
            int r0 = bm + wr * 32 + mi * 16 + g;
            float2 o0, o1;
            o0.x = acc[mi][nj][0] * scale + bx;
            o0.y = acc[mi][nj][1] * scale + by;
            o1.x = acc[mi][nj][2] * scale + bx;
            o1.y = acc[mi][nj][3] * scale + by;
            *(float2*)&Cp[(size_t)r0 * ldc + col] = o0;
            *(float2*)&Cp[(size_t)(r0 + 8) * ldc + col] = o1;
        }
    }
}

// ---------------- Launch ----------------
static void run_gemm(const bf16* Ah, const bf16* Al, const bf16* Bh, const bf16* Bl,
                     const float* bias, float* C, int M, int N, int K, int batches,
                     long long sA, long long sB, long long sCb, long long sCh,
                     int ldc, float scale)
{
    mma_gemm_kernel<<<dim3(N / 64, M / 128, batches), 256, GEMM_SMEM>>>(
        Ah, Al, Bh, Bl, bias, C, K, ldc, sA, sB, sCb, sCh, scale);
}

extern "C" void kernel_launch(void* const* d_in, const int* in_sizes, int n_in,
                              void* d_out, int out_size)
{
    const float* x        = (const float*)d_in[0];
    const int*   pos      = (const int*)d_in[1];
    const float* w_dq_w   = (const float*)d_in[2];
    const float* w_dq_b   = (const float*)d_in[3];
    const float* q_norm_w = (const float*)d_in[4];
    const float* w_uq_w   = (const float*)d_in[5];
    const float* w_uq_b   = (const float*)d_in[6];
    const float* w_dkv_w  = (const float*)d_in[7];
    const float* w_dkv_b  = (const float*)d_in[8];
    const float* kv_norm_w= (const float*)d_in[9];
    const float* w_ukv_w  = (const float*)d_in[10];
    const float* w_ukv_b  = (const float*)d_in[11];
    const float* w_o_w    = (const float*)d_in[12];
    const float* w_o_b    = (const float*)d_in[13];
    float* out = (float*)d_out;

    cudaFuncSetAttribute(mma_gemm_kernel, cudaFuncAttributeMaxDynamicSharedMemorySize, GEMM_SMEM);

    float *cq, *q, *ckvkr, *kv, *attn, *S;
    bf16 *xh, *xl, *cqh, *cql, *ckvh, *ckvl, *Qh, *Ql, *Kh, *Kl, *Vth, *Vtl, *Ph, *Pl;
    bf16 *attnh, *attnl, *wdqh, *wdql, *wuqh, *wuql, *wdkvh, *wdkvl, *wukvh, *wukvl, *woh, *wol;
    cudaGetSymbolAddress((void**)&cq, g_cq);       cudaGetSymbolAddress((void**)&q, g_q);
    cudaGetSymbolAddress((void**)&ckvkr, g_ckvkr); cudaGetSymbolAddress((void**)&kv, g_kv);
    cudaGetSymbolAddress((void**)&attn, g_attn);   cudaGetSymbolAddress((void**)&S, g_S);
    cudaGetSymbolAddress((void**)&xh, g_xh);       cudaGetSymbolAddress((void**)&xl, g_xl);
    cudaGetSymbolAddress((void**)&cqh, g_cqh);     cudaGetSymbolAddress((void**)&cql, g_cql);
    cudaGetSymbolAddress((void**)&ckvh, g_ckvh);   cudaGetSymbolAddress((void**)&ckvl, g_ckvl);
    cudaGetSymbolAddress((void**)&Qh, g_Qh);       cudaGetSymbolAddress((void**)&Ql, g_Ql);
    cudaGetSymbolAddress((void**)&Kh, g_Kh);       cudaGetSymbolAddress((void**)&Kl, g_Kl);
    cudaGetSymbolAddress((void**)&Vth, g_Vth);     cudaGetSymbolAddress((void**)&Vtl, g_Vtl);
    cudaGetSymbolAddress((void**)&Ph, g_Ph);       cudaGetSymbolAddress((void**)&Pl, g_Pl);
    cudaGetSymbolAddress((void**)&attnh, g_attnh); cudaGetSymbolAddress((void**)&attnl, g_attnl);
    cudaGetSymbolAddress((void**)&wdqh, g_wdqh);   cudaGetSymbolAddress((void**)&wdql, g_wdql);
    cudaGetSymbolAddress((void**)&wuqh, g_wuqh);   cudaGetSymbolAddress((void**)&wuql, g_wuql);
    cudaGetSymbolAddress((void**)&wdkvh, g_wdkvh); cudaGetSymbolAddress((void**)&wdkvl, g_wdkvl);
    cudaGetSymbolAddress((void**)&wukvh, g_wukvh); cudaGetSymbolAddress((void**)&wukvl, g_wukvl);
    cudaGetSymbolAddress((void**)&woh, g_woh);     cudaGetSymbolAddress((void**)&wol, g_wol);

    // Operand conversions
    convert_split_kernel<<<(BS * DIM / 4) / 256, 256>>>(x, xh, xl, BS * DIM / 4);
    transpose_split_kernel<<<dim3(QC / 32, DIM / 32), dim3(32, 8)>>>(w_dq_w, DIM, QC, wdqh, wdql);
    transpose_split_kernel<<<dim3((NH * DQK) / 32, QC / 32), dim3(32, 8)>>>(w_uq_w, QC, NH * DQK, wuqh, wuql);
    transpose_split_kernel<<<dim3((KVC + KROPE) / 32, DIM / 32), dim3(32, 8)>>>(w_dkv_w, DIM, KVC + KROPE, wdkvh, wdkvl);
    transpose_split_kernel<<<dim3((NH * (KNOPE + VHD)) / 32, KVC / 32), dim3(32, 8)>>>(w_ukv_w, KVC, NH * (KNOPE + VHD), wukvh, wukvl);
    transpose_split_kernel<<<dim3(DIM / 32, (NH * VHD) / 32), dim3(32, 8)>>>(w_o_w, NH * VHD, DIM, woh, wol);

    // 1) cq_raw = x @ w_dq + b
    run_gemm(xh, xl, wdqh, wdql, w_dq_b, cq, BS, QC, DIM, 1, 0, 0, 0, 0, QC, 1.f);
    // 2) cq = rmsnorm(cq_raw) -> hi/lo
    rmsnorm_split_kernel<<<BS, 128>>>(cq, QC, q_norm_w, cqh, cql);
    // 3) q = cq @ w_uq + b
    run_gemm(cqh, cql, wuqh, wuql, w_uq_b, q, BS, NH * DQK, QC, 1, 0, 0, 0, 0, NH * DQK, 1.f);
    // 4) ckv_kr = x @ w_dkv + b
    run_gemm(xh, xl, wdkvh, wdkvl, w_dkv_b, ckvkr, BS, KVC + KROPE, DIM, 1, 0, 0, 0, 0, KVC + KROPE, 1.f);
    // 5) ckv = rmsnorm(ckv_kr[:, :128]) -> hi/lo
    rmsnorm_split_kernel<<<BS, 128>>>(ckvkr, KVC + KROPE, kv_norm_w, ckvh, ckvl);
    // 6) kv = ckv @ w_ukv + b
    run_gemm(ckvh, ckvl, wukvh, wukvl, w_ukv_b, kv, BS, NH * (KNOPE + VHD), KVC, 1, 0, 0, 0, 0, NH * (KNOPE + VHD), 1.f);
    // 7-9) assemble Q / K / V^T
    assemble_q_kernel<<<dim3(SEQ, BATCH * NH), 128>>>(pos);
    assemble_k_kernel<<<dim3(SEQ, BATCH), 128>>>(pos);
    vt_split_kernel<<<dim3(SEQ / 32, VHD / 32, BATCH * NH), dim3(32, 8)>>>();
    // 10) S = scale * Q @ K^T   (batched over 16 bh)
    run_gemm(Qh, Ql, Kh, Kl, nullptr, S, SEQ, SEQ, DQK, BATCH * NH,
             (long long)SEQ * DQK, (long long)SEQ * DQK,
             8LL * SEQ * SEQ, (long long)SEQ * SEQ, SEQ, SOFTMAX_SCALE);
    // 11) P = softmax(S) -> hi/lo
    softmax_split_kernel<<<16 * SEQ, 256>>>();
    // 12) attn[b*S+q][h*256+n] = P @ V
    run_gemm(Ph, Pl, Vth, Vtl, nullptr, attn, SEQ, VHD, SEQ, BATCH * NH,
             (long long)SEQ * SEQ, (long long)VHD * SEQ,
             (long long)SEQ * (NH * VHD), (long long)VHD, NH * VHD, 1.f);
    // 13) attn -> hi/lo
    convert_split_kernel<<<(BS * NH * VHD / 4) / 256, 256>>>(attn, attnh, attnl, BS * NH * VHD / 4);
    // 14) out = attn @ w_o + b
    run_gemm(attnh, attnl, woh, wol, w_o_b, out, BS, DIM, NH * VHD, 1, 0, 0, 0, 0, DIM, 1.f);
}